// round 16
// baseline (speedup 1.0000x reference)
#include <cuda_runtime.h>
#include <cuda_fp16.h>
#include <math.h>
#include <stdint.h>

#define TT 4096
#define HH 2048
#define NH 16
#define NKV 8
#define HD 128
#define QS 2048
#define KVS 1024
#define QKVN 4096

// ---------------- scratch (device globals; no allocation allowed) ----------
__device__ float  g_qkv[(size_t)TT * QKVN];   // qkv projection output (fp32)
__device__ __half g_hst[(size_t)TT * HH];     // hidden_states fp16
__device__ __half g_wqT[(size_t)QKVN * HH];   // w_qkv transposed [N][K] fp16
__device__ __half g_woT[(size_t)HH * QS];     // w_o transposed [N][K] fp16
__device__ __half g_q[(size_t)TT * QS];       // normed+roped Q fp16 (pre-scaled)
__device__ __half g_k[(size_t)TT * KVS];      // normed+roped K fp16
__device__ __half g_vT[(size_t)KVS * TT];     // V transposed [kv*HD][T] fp16
__device__ __half g_att[(size_t)TT * QS];     // attention out fp16

// ---------------- helpers ---------------------------------------------------
__device__ __forceinline__ float ex2(float x) {
    float r;
    asm("ex2.approx.f32 %0, %1;" : "=f"(r) : "f"(x));
    return r;
}

__device__ __forceinline__ unsigned pkh2(float a, float b) {
    __half2 h = __floats2half2_rn(a, b);
    return *reinterpret_cast<unsigned*>(&h);
}

__device__ __forceinline__ void mma16(float* c, unsigned a0, unsigned a1,
                                      unsigned a2, unsigned a3,
                                      unsigned b0, unsigned b1) {
    asm volatile(
        "mma.sync.aligned.m16n8k16.row.col.f32.f16.f16.f32 "
        "{%0,%1,%2,%3},{%4,%5,%6,%7},{%8,%9},{%0,%1,%2,%3};"
        : "+f"(c[0]), "+f"(c[1]), "+f"(c[2]), "+f"(c[3])
        : "r"(a0), "r"(a1), "r"(a2), "r"(a3), "r"(b0), "r"(b1));
}

__device__ __forceinline__ void ldm4(unsigned* r, uint32_t a) {
    asm volatile("ldmatrix.sync.aligned.m8n8.x4.shared.b16 {%0,%1,%2,%3}, [%4];"
                 : "=r"(r[0]), "=r"(r[1]), "=r"(r[2]), "=r"(r[3]) : "r"(a));
}

__device__ __forceinline__ uint32_t smem_u32(const void* p) {
    uint32_t a;
    asm("{ .reg .u64 t; cvta.to.shared.u64 t, %1; cvt.u32.u64 %0, t; }"
        : "=r"(a) : "l"(p));
    return a;
}

__device__ __forceinline__ void cpa16(uint32_t dst, const void* src) {
    asm volatile("cp.async.cg.shared.global [%0], [%1], 16;"
                 :: "r"(dst), "l"(src));
}
#define CP_COMMIT() asm volatile("cp.async.commit_group;" ::: "memory")
#define CP_WAIT(n) asm volatile("cp.async.wait_group %0;" :: "n"(n) : "memory")

// ---------------- fp16 convert / transpose kernels --------------------------
__global__ void cvt_h(const float* __restrict__ s, __half2* __restrict__ d,
                      int n2) {
    int i = blockIdx.x * blockDim.x + threadIdx.x;
    if (i < n2) {
        float2 v = ((const float2*)s)[i];
        d[i] = __floats2half2_rn(v.x, v.y);
    }
}

// src [R][C] fp32 -> dst [C][R] fp16 (R, C multiples of 32)
__global__ void cvt_t(const float* __restrict__ s, __half* __restrict__ d,
                      int R, int C) {
    __shared__ float tile[32][33];
    int c0 = blockIdx.x * 32, r0 = blockIdx.y * 32;
    for (int i = threadIdx.y; i < 32; i += 8)
        tile[i][threadIdx.x] = s[(size_t)(r0 + i) * C + c0 + threadIdx.x];
    __syncthreads();
    for (int i = threadIdx.y; i < 32; i += 8)
        d[(size_t)(c0 + i) * R + r0 + threadIdx.x] =
            __float2half(tile[threadIdx.x][i]);
}

// V region of g_qkv ([T][KVS] with row stride QKVN) -> g_vT [KVS][T] fp16
__global__ void cvt_tv() {
    __shared__ float tile[32][33];
    int c0 = blockIdx.x * 32, r0 = blockIdx.y * 32;   // r = token, c = v-col
    for (int i = threadIdx.y; i < 32; i += 8)
        tile[i][threadIdx.x] =
            g_qkv[(size_t)(r0 + i) * QKVN + (QS + KVS) + c0 + threadIdx.x];
    __syncthreads();
    for (int i = threadIdx.y; i < 32; i += 8)
        g_vT[(size_t)(c0 + i) * TT + r0 + threadIdx.x] =
            __float2half(tile[threadIdx.x][i]);
}

// ---------------- fp16 mma GEMM (R12-proven): BM=BN=128, BK=64 --------------
// 8 warps (2m x 4n), warp tile 64x32; 3-stage cp.async, 1 barrier/ktile,
// 2 CTAs/SM.
#define ASTRH 72                       // halves per smem row (64 + 8 pad)
#define STGH (2 * 128 * ASTRH)         // halves per stage (A + B) = 18432
#define GM_SMEM_BYTES (3 * STGH * 2)   // 110592

__global__ __launch_bounds__(256, 2)
void gemm_h(const __half* __restrict__ A, const __half* __restrict__ Bt,
            float* __restrict__ C, int M, int N, int K) {
    extern __shared__ __half smh[];
    uint32_t sb = smem_u32(smh);

    int tid = threadIdx.x;
    int w = tid >> 5, lane = tid & 31;
    int g = lane >> 2, t = lane & 3;
    int wm = (w >> 2) * 64, wn = (w & 3) * 32;
    int m0 = blockIdx.y * 128, n0 = blockIdx.x * 128;

    int lr = tid >> 3, lc = (tid & 7) * 8;   // loader: 32 rows/iter x 8 chunks

    int lane8 = lane & 7, lg = lane >> 3;
    int arow = lane & 15, acol = (lane >> 4) * 8;
    int brow = (lg >> 1) * 8 + lane8, bcol = (lg & 1) * 8;

    float acc[4][4][4];
#pragma unroll
    for (int mt = 0; mt < 4; mt++)
#pragma unroll
        for (int nt = 0; nt < 4; nt++)
#pragma unroll
            for (int r = 0; r < 4; r++) acc[mt][nt][r] = 0.f;

    int nkt = K / 64;
#pragma unroll
    for (int p = 0; p < 2; p++) {
        uint32_t ab = sb + p * STGH * 2;
        uint32_t bb = ab + 128 * ASTRH * 2;
#pragma unroll
        for (int i = 0; i < 4; i++) {
            int r = lr + 32 * i;
            cpa16(ab + (r * ASTRH + lc) * 2, &A[(size_t)(m0 + r) * K + p * 64 + lc]);
            cpa16(bb + (r * ASTRH + lc) * 2, &Bt[(size_t)(n0 + r) * K + p * 64 + lc]);
        }
        CP_COMMIT();
    }

    for (int kt = 0; kt < nkt; kt++) {
        CP_WAIT(1);
        __syncthreads();

        uint32_t abase = sb + (kt % 3) * STGH * 2;
        uint32_t bbase = abase + 128 * ASTRH * 2;
#pragma unroll
        for (int ks = 0; ks < 4; ks++) {
            unsigned a[4][4], bp[2][4];
#pragma unroll
            for (int mt = 0; mt < 4; mt++)
                ldm4(a[mt],
                     abase + ((wm + mt * 16 + arow) * ASTRH + acol + ks * 16) * 2);
#pragma unroll
            for (int np = 0; np < 2; np++)
                ldm4(bp[np],
                     bbase + ((wn + np * 16 + brow) * ASTRH + bcol + ks * 16) * 2);
#pragma unroll
            for (int mt = 0; mt < 4; mt++)
#pragma unroll
                for (int nt = 0; nt < 4; nt++)
                    mma16(acc[mt][nt], a[mt][0], a[mt][1], a[mt][2], a[mt][3],
                          bp[nt >> 1][(nt & 1) * 2], bp[nt >> 1][(nt & 1) * 2 + 1]);
        }

        if (kt + 2 < nkt) {
            int st = (kt + 2) % 3;
            uint32_t ab = sb + st * STGH * 2;
            uint32_t bb = ab + 128 * ASTRH * 2;
            int kof = (kt + 2) * 64;
#pragma unroll
            for (int i = 0; i < 4; i++) {
                int r = lr + 32 * i;
                cpa16(ab + (r * ASTRH + lc) * 2,
                      &A[(size_t)(m0 + r) * K + kof + lc]);
                cpa16(bb + (r * ASTRH + lc) * 2,
                      &Bt[(size_t)(n0 + r) * K + kof + lc]);
            }
        }
        CP_COMMIT();
    }

#pragma unroll
    for (int mt = 0; mt < 4; mt++)
#pragma unroll
        for (int nt = 0; nt < 4; nt++) {
            int row = m0 + wm + mt * 16 + g;
            int col = n0 + wn + nt * 8 + 2 * t;
            *(float2*)&C[(size_t)row * N + col] =
                make_float2(acc[mt][nt][0], acc[mt][nt][1]);
            *(float2*)&C[(size_t)(row + 8) * N + col] =
                make_float2(acc[mt][nt][2], acc[mt][nt][3]);
        }
}

// ---------------- per-head RMSNorm + RoPE -> fp16 (warp per (token,head)) ---
__global__ void normrope(const int* __restrict__ pos,
                         const float* __restrict__ qw,
                         const float* __restrict__ kw) {
    int gw = (blockIdx.x * blockDim.x + threadIdx.x) >> 5;
    int lane = threadIdx.x & 31;
    if (gw >= TT * (NH + NKV)) return;
    int t = gw / (NH + NKV);
    int hh = gw - t * (NH + NKV);

    const float* src;
    __half* dst;
    const float* w;
    float osc;
    const float QSC = 0.08838834764831845f * 1.4426950408889634f; // scale*log2e
    if (hh < NH) {
        src = g_qkv + (size_t)t * QKVN + hh * HD;
        dst = g_q + (size_t)t * QS + hh * HD;
        w = qw;
        osc = QSC;
    } else {
        int kk = hh - NH;
        src = g_qkv + (size_t)t * QKVN + QS + kk * HD;
        dst = g_k + (size_t)t * KVS + kk * HD;
        w = kw;
        osc = 1.0f;
    }
    float v0 = src[lane], v1 = src[lane + 32], v2 = src[lane + 64], v3 = src[lane + 96];
    float ss = v0 * v0 + v1 * v1 + v2 * v2 + v3 * v3;
#pragma unroll
    for (int o = 16; o; o >>= 1) ss += __shfl_xor_sync(0xffffffffu, ss, o);
    float inv = rsqrtf(ss * (1.0f / 128.0f) + 1e-6f);
    v0 *= inv * w[lane];
    v1 *= inv * w[lane + 32];
    v2 *= inv * w[lane + 64];
    v3 *= inv * w[lane + 96];

    float p = (float)pos[t];
    const float LOG2_THETA = 19.931568569324174f;
    float if0 = exp2f(-LOG2_THETA * (2.0f * lane) * (1.0f / 128.0f));
    float if1 = exp2f(-LOG2_THETA * (2.0f * (lane + 32)) * (1.0f / 128.0f));
    float s0, c0, s1, c1;
    sincosf(p * if0, &s0, &c0);
    sincosf(p * if1, &s1, &c1);
    dst[lane]      = __float2half((v0 * c0 - v2 * s0) * osc);
    dst[lane + 64] = __float2half((v2 * c0 + v0 * s0) * osc);
    dst[lane + 32] = __float2half((v1 * c1 - v3 * s1) * osc);
    dst[lane + 96] = __float2half((v3 * c1 + v1 * s1) * osc);
}

// ---------------- fp16 flash attention: BM=64, BN=64, 2 CTAs/SM -------------
// 128 threads = 4 warps x 16 q-rows, each warp covers all 64 kv cols.
// Small CTA => 2 resident CTAs overlap softmax with the other CTA's mma.
#define KSTR2 136
#define VSTR2 72
#define QSTR2 136
#define KSZ2 (64 * KSTR2)    // 8704 halves
#define VSZ2 (128 * VSTR2)   // 9216 halves
#define QSZ2 (64 * QSTR2)    // 8704 halves
#define FL_SMEM_BYTES ((2 * KSZ2 + 2 * VSZ2 + QSZ2) * 2)  // 89088

__global__ __launch_bounds__(128, 2)
void flash_h(const __half* __restrict__ gq, const __half* __restrict__ gk,
             const __half* __restrict__ gvT) {
    extern __shared__ __half smf[];
    uint32_t sb = smem_u32(smf);
    uint32_t kbA[2] = {sb, sb + KSZ2 * 2};
    uint32_t vbA[2] = {sb + 2 * KSZ2 * 2, sb + (2 * KSZ2 + VSZ2) * 2};
    uint32_t qbase = sb + (2 * KSZ2 + 2 * VSZ2) * 2;
    __half* Qs = smf + 2 * KSZ2 + 2 * VSZ2;

    int tid = threadIdx.x, w = tid >> 5, lane = tid & 31;
    int g = lane >> 2, t = lane & 3;
    int qt = gridDim.x - 1 - blockIdx.x;   // heavy tiles first
    int h = blockIdx.y, kvh = h >> 1;
    int q0 = qt * 64;

    int lane8 = lane & 7, lg = lane >> 3;
    int arow = lane & 15, acol = (lane >> 4) * 8;
    int brow = (lg >> 1) * 8 + lane8, bcol = (lg & 1) * 8;

    // prefetch K/V tile 0 (K: [64 tok][128 d]; V: [128 d][64 tok])
#pragma unroll
    for (int i = 0; i < 8; i++) {
        int idx = tid + 128 * i;
        int kr = idx >> 4, kc = (idx & 15) * 8;
        cpa16(kbA[0] + (kr * KSTR2 + kc) * 2,
              &gk[(size_t)kr * KVS + kvh * HD + kc]);
        int vr = idx >> 3, vc = (idx & 7) * 8;
        cpa16(vbA[0] + (vr * VSTR2 + vc) * 2,
              &gvT[(size_t)(kvh * HD + vr) * TT + vc]);
    }
    CP_COMMIT();

    // stage Q tile (fp16, pre-scaled), then fragments -> registers
    for (int idx = tid; idx < 64 * 16; idx += 128) {
        int r = idx >> 4, cq = (idx & 15) * 8;
        *(uint4*)&Qs[r * QSTR2 + cq] =
            *(const uint4*)&gq[(size_t)(q0 + r) * QS + h * HD + cq];
    }
    __syncthreads();
    unsigned qa[8][4];
#pragma unroll
    for (int ks = 0; ks < 8; ks++)
        ldm4(qa[ks], qbase + ((w * 16 + arow) * QSTR2 + ks * 16 + acol) * 2);

    float m_[2] = {-INFINITY, -INFINITY};
    float l_[2] = {0.f, 0.f};
    float O[16][4];
#pragma unroll
    for (int dt = 0; dt < 16; dt++)
#pragma unroll
        for (int r = 0; r < 4; r++) O[dt][r] = 0.f;

    for (int kt = 0; kt <= qt; kt++) {
        int cur = kt & 1;
        if (kt < qt) {
            int nb = cur ^ 1, k0n = (kt + 1) * 64;
#pragma unroll
            for (int i = 0; i < 8; i++) {
                int idx = tid + 128 * i;
                int kr = idx >> 4, kc = (idx & 15) * 8;
                cpa16(kbA[nb] + (kr * KSTR2 + kc) * 2,
                      &gk[(size_t)(k0n + kr) * KVS + kvh * HD + kc]);
                int vr = idx >> 3, vc = (idx & 7) * 8;
                cpa16(vbA[nb] + (vr * VSTR2 + vc) * 2,
                      &gvT[(size_t)(kvh * HD + vr) * TT + k0n + vc]);
            }
        }
        CP_COMMIT();
        CP_WAIT(1);
        __syncthreads();

        uint32_t kcur = kbA[cur], vcur = vbA[cur];
        int k0 = kt * 64;

        // S = Q K^T (64 cols)
        float s[8][4];
#pragma unroll
        for (int nt = 0; nt < 8; nt++)
#pragma unroll
            for (int r = 0; r < 4; r++) s[nt][r] = 0.f;
#pragma unroll
        for (int ks = 0; ks < 8; ks++) {
#pragma unroll
            for (int p = 0; p < 4; p++) {
                unsigned kb[4];
                ldm4(kb, kcur + ((p * 16 + brow) * KSTR2 + bcol + ks * 16) * 2);
                mma16(s[2 * p], qa[ks][0], qa[ks][1], qa[ks][2], qa[ks][3],
                      kb[0], kb[1]);
                mma16(s[2 * p + 1], qa[ks][0], qa[ks][1], qa[ks][2], qa[ks][3],
                      kb[2], kb[3]);
            }
        }

        // causal mask (diagonal tile only: k0 == q0; every row keeps >=1 col)
        if (kt == qt) {
            int row0 = q0 + w * 16 + g, row1 = row0 + 8;
#pragma unroll
            for (int nt = 0; nt < 8; nt++) {
                int c0 = k0 + nt * 8 + 2 * t, c1 = c0 + 1;
                if (c0 > row0) s[nt][0] = -1e30f;
                if (c1 > row0) s[nt][1] = -1e30f;
                if (c0 > row1) s[nt][2] = -1e30f;
                if (c1 > row1) s[nt][3] = -1e30f;
            }
        }

        // online softmax, base-2 domain (log2e folded into Q scale)
        float mx0 = -INFINITY, mx1 = -INFINITY;
#pragma unroll
        for (int nt = 0; nt < 8; nt++) {
            mx0 = fmaxf(mx0, fmaxf(s[nt][0], s[nt][1]));
            mx1 = fmaxf(mx1, fmaxf(s[nt][2], s[nt][3]));
        }
        mx0 = fmaxf(mx0, __shfl_xor_sync(0xffffffffu, mx0, 1));
        mx0 = fmaxf(mx0, __shfl_xor_sync(0xffffffffu, mx0, 2));
        mx1 = fmaxf(mx1, __shfl_xor_sync(0xffffffffu, mx1, 1));
        mx1 = fmaxf(mx1, __shfl_xor_sync(0xffffffffu, mx1, 2));
        float mn0 = fmaxf(m_[0], mx0), mn1 = fmaxf(m_[1], mx1);
        float al0 = ex2(m_[0] - mn0), al1 = ex2(m_[1] - mn1);
        m_[0] = mn0; m_[1] = mn1;
        float sum0 = 0.f, sum1 = 0.f;
#pragma unroll
        for (int nt = 0; nt < 8; nt++) {
            s[nt][0] = ex2(s[nt][0] - mn0);
            s[nt][1] = ex2(s[nt][1] - mn0);
            s[nt][2] = ex2(s[nt][2] - mn1);
            s[nt][3] = ex2(s[nt][3] - mn1);
            sum0 += s[nt][0] + s[nt][1];
            sum1 += s[nt][2] + s[nt][3];
        }
        sum0 += __shfl_xor_sync(0xffffffffu, sum0, 1);
        sum0 += __shfl_xor_sync(0xffffffffu, sum0, 2);
        sum1 += __shfl_xor_sync(0xffffffffu, sum1, 1);
        sum1 += __shfl_xor_sync(0xffffffffu, sum1, 2);
        l_[0] = al0 * l_[0] + sum0;
        l_[1] = al1 * l_[1] + sum1;
#pragma unroll
        for (int dt = 0; dt < 16; dt++) {
            O[dt][0] *= al0; O[dt][1] *= al0;
            O[dt][2] *= al1; O[dt][3] *= al1;
        }

        // O += P V  — P packed straight from registers; V frags via ldmatrix
#pragma unroll
        for (int ks2 = 0; ks2 < 4; ks2++) {
            unsigned a0 = pkh2(s[2 * ks2][0], s[2 * ks2][1]);
            unsigned a1 = pkh2(s[2 * ks2][2], s[2 * ks2][3]);
            unsigned a2 = pkh2(s[2 * ks2 + 1][0], s[2 * ks2 + 1][1]);
            unsigned a3 = pkh2(s[2 * ks2 + 1][2], s[2 * ks2 + 1][3]);
#pragma unroll
            for (int p = 0; p < 8; p++) {
                unsigned vb[4];
                ldm4(vb, vcur + ((p * 16 + brow) * VSTR2 + bcol + ks2 * 16) * 2);
                mma16(O[2 * p], a0, a1, a2, a3, vb[0], vb[1]);
                mma16(O[2 * p + 1], a0, a1, a2, a3, vb[2], vb[3]);
            }
        }
        __syncthreads();
    }

    // epilogue -> fp16 g_att
    float i0 = 1.f / l_[0], i1 = 1.f / l_[1];
    int row0 = q0 + w * 16 + g;
    __half2* at2 = (__half2*)g_att;
#pragma unroll
    for (int dt = 0; dt < 16; dt++) {
        int col2 = (h * HD + dt * 8 + 2 * t) >> 1;
        at2[(size_t)row0 * (QS / 2) + col2] =
            __floats2half2_rn(O[dt][0] * i0, O[dt][1] * i0);
        at2[(size_t)(row0 + 8) * (QS / 2) + col2] =
            __floats2half2_rn(O[dt][2] * i1, O[dt][3] * i1);
    }
}

// ---------------------------------------------------------------------------
extern "C" void kernel_launch(void* const* d_in, const int* in_sizes, int n_in,
                              void* d_out, int out_size) {
    const int* positions = (const int*)d_in[0];
    const float* hs = (const float*)d_in[1];
    const float* w_qkv = (const float*)d_in[2];
    const float* w_o = (const float*)d_in[3];
    const float* qw = (const float*)d_in[4];
    const float* kw = (const float*)d_in[5];
    float* out = (float*)d_out;

    float* p_qkv;
    __half *p_hst, *p_wqT, *p_woT, *p_q, *p_k, *p_vT, *p_att;
    cudaGetSymbolAddress((void**)&p_qkv, g_qkv);
    cudaGetSymbolAddress((void**)&p_hst, g_hst);
    cudaGetSymbolAddress((void**)&p_wqT, g_wqT);
    cudaGetSymbolAddress((void**)&p_woT, g_woT);
    cudaGetSymbolAddress((void**)&p_q, g_q);
    cudaGetSymbolAddress((void**)&p_k, g_k);
    cudaGetSymbolAddress((void**)&p_vT, g_vT);
    cudaGetSymbolAddress((void**)&p_att, g_att);
    cudaFuncSetAttribute(gemm_h,
                         cudaFuncAttributeMaxDynamicSharedMemorySize, GM_SMEM_BYTES);
    cudaFuncSetAttribute(flash_h,
                         cudaFuncAttributeMaxDynamicSharedMemorySize, FL_SMEM_BYTES);

    // 0) fp16 conversion / weight transposes
    cvt_h<<<(TT * HH / 2 + 255) / 256, 256>>>(hs, (__half2*)p_hst, TT * HH / 2);
    cvt_t<<<dim3(QKVN / 32, HH / 32), dim3(32, 8)>>>(w_qkv, p_wqT, HH, QKVN);
    cvt_t<<<dim3(HH / 32, QS / 32), dim3(32, 8)>>>(w_o, p_woT, QS, HH);
    // 1) QKV projection (fp16 mma, fp32 out)
    gemm_h<<<dim3(QKVN / 128, TT / 128), 256, GM_SMEM_BYTES>>>(
        p_hst, p_wqT, p_qkv, TT, QKVN, HH);
    // 2) per-head RMSNorm + RoPE -> fp16 Q/K ; V transpose -> fp16
    normrope<<<(TT * (NH + NKV)) / 8, 256>>>(positions, qw, kw);
    cvt_tv<<<dim3(KVS / 32, TT / 32), dim3(32, 8)>>>();
    // 3) causal GQA flash attention (fp16 mma, BM=64/BN=64, 2 CTAs/SM)
    flash_h<<<dim3(TT / 64, NH), 128, FL_SMEM_BYTES>>>(p_q, p_k, p_vT);
    // 4) output projection
    gemm_h<<<dim3(HH / 128, TT / 128), 256, GM_SMEM_BYTES>>>(
        p_att, p_woT, out, TT, HH, QS);
}

// round 17
// speedup vs baseline: 1.5372x; 1.5372x over previous
#include <cuda_runtime.h>
#include <cuda_fp16.h>
#include <math.h>
#include <stdint.h>

#define TT 4096
#define HH 2048
#define NH 16
#define NKV 8
#define HD 128
#define QS 2048
#define KVS 1024
#define QKVN 4096

// ---------------- scratch (device globals; no allocation allowed) ----------
__device__ float  g_qkv[(size_t)TT * QKVN];   // qkv projection output (fp32)
__device__ __half g_hst[(size_t)TT * HH];     // hidden_states fp16
__device__ __half g_wqT[(size_t)QKVN * HH];   // w_qkv transposed [N][K] fp16
__device__ __half g_woT[(size_t)HH * QS];     // w_o transposed [N][K] fp16
__device__ __half g_q[(size_t)TT * QS];       // normed+roped Q fp16 (pre-scaled)
__device__ __half g_k[(size_t)TT * KVS];      // normed+roped K fp16
__device__ __half g_vT[(size_t)KVS * TT];     // V transposed [kv*HD][T] fp16
__device__ __half g_att[(size_t)TT * QS];     // attention out fp16

// ---------------- helpers ---------------------------------------------------
__device__ __forceinline__ float ex2(float x) {
    float r;
    asm("ex2.approx.f32 %0, %1;" : "=f"(r) : "f"(x));
    return r;
}

__device__ __forceinline__ unsigned pkh2(float a, float b) {
    __half2 h = __floats2half2_rn(a, b);
    return *reinterpret_cast<unsigned*>(&h);
}

__device__ __forceinline__ void mma16(float* c, unsigned a0, unsigned a1,
                                      unsigned a2, unsigned a3,
                                      unsigned b0, unsigned b1) {
    asm volatile(
        "mma.sync.aligned.m16n8k16.row.col.f32.f16.f16.f32 "
        "{%0,%1,%2,%3},{%4,%5,%6,%7},{%8,%9},{%0,%1,%2,%3};"
        : "+f"(c[0]), "+f"(c[1]), "+f"(c[2]), "+f"(c[3])
        : "r"(a0), "r"(a1), "r"(a2), "r"(a3), "r"(b0), "r"(b1));
}

__device__ __forceinline__ void ldm4(unsigned* r, uint32_t a) {
    asm volatile("ldmatrix.sync.aligned.m8n8.x4.shared.b16 {%0,%1,%2,%3}, [%4];"
                 : "=r"(r[0]), "=r"(r[1]), "=r"(r[2]), "=r"(r[3]) : "r"(a));
}

__device__ __forceinline__ uint32_t smem_u32(const void* p) {
    uint32_t a;
    asm("{ .reg .u64 t; cvta.to.shared.u64 t, %1; cvt.u32.u64 %0, t; }"
        : "=r"(a) : "l"(p));
    return a;
}

__device__ __forceinline__ void cpa16(uint32_t dst, const void* src) {
    asm volatile("cp.async.cg.shared.global [%0], [%1], 16;"
                 :: "r"(dst), "l"(src));
}
#define CP_COMMIT() asm volatile("cp.async.commit_group;" ::: "memory")
#define CP_WAIT(n) asm volatile("cp.async.wait_group %0;" :: "n"(n) : "memory")

// ---------------- fp16 convert / transpose kernels --------------------------
__global__ void cvt_h(const float* __restrict__ s, __half2* __restrict__ d,
                      int n2) {
    int i = blockIdx.x * blockDim.x + threadIdx.x;
    if (i < n2) {
        float2 v = ((const float2*)s)[i];
        d[i] = __floats2half2_rn(v.x, v.y);
    }
}

// src [R][C] fp32 -> dst [C][R] fp16 (R, C multiples of 32)
__global__ void cvt_t(const float* __restrict__ s, __half* __restrict__ d,
                      int R, int C) {
    __shared__ float tile[32][33];
    int c0 = blockIdx.x * 32, r0 = blockIdx.y * 32;
    for (int i = threadIdx.y; i < 32; i += 8)
        tile[i][threadIdx.x] = s[(size_t)(r0 + i) * C + c0 + threadIdx.x];
    __syncthreads();
    for (int i = threadIdx.y; i < 32; i += 8)
        d[(size_t)(c0 + i) * R + r0 + threadIdx.x] =
            __float2half(tile[threadIdx.x][i]);
}

// V region of g_qkv ([T][KVS] with row stride QKVN) -> g_vT [KVS][T] fp16
__global__ void cvt_tv() {
    __shared__ float tile[32][33];
    int c0 = blockIdx.x * 32, r0 = blockIdx.y * 32;   // r = token, c = v-col
    for (int i = threadIdx.y; i < 32; i += 8)
        tile[i][threadIdx.x] =
            g_qkv[(size_t)(r0 + i) * QKVN + (QS + KVS) + c0 + threadIdx.x];
    __syncthreads();
    for (int i = threadIdx.y; i < 32; i += 8)
        g_vT[(size_t)(c0 + i) * TT + r0 + threadIdx.x] =
            __float2half(tile[threadIdx.x][i]);
}

// ---------------- fp16 mma GEMM (R12-proven): BM=BN=128, BK=64 --------------
// 8 warps (2m x 4n), warp tile 64x32; 3-stage cp.async, 1 barrier/ktile,
// 2 CTAs/SM.
#define ASTRH 72                       // halves per smem row (64 + 8 pad)
#define STGH (2 * 128 * ASTRH)         // halves per stage (A + B) = 18432
#define GM_SMEM_BYTES (3 * STGH * 2)   // 110592

__global__ __launch_bounds__(256, 2)
void gemm_h(const __half* __restrict__ A, const __half* __restrict__ Bt,
            float* __restrict__ C, int M, int N, int K) {
    extern __shared__ __half smh[];
    uint32_t sb = smem_u32(smh);

    int tid = threadIdx.x;
    int w = tid >> 5, lane = tid & 31;
    int g = lane >> 2, t = lane & 3;
    int wm = (w >> 2) * 64, wn = (w & 3) * 32;
    int m0 = blockIdx.y * 128, n0 = blockIdx.x * 128;

    int lr = tid >> 3, lc = (tid & 7) * 8;   // loader: 32 rows/iter x 8 chunks

    int lane8 = lane & 7, lg = lane >> 3;
    int arow = lane & 15, acol = (lane >> 4) * 8;
    int brow = (lg >> 1) * 8 + lane8, bcol = (lg & 1) * 8;

    float acc[4][4][4];
#pragma unroll
    for (int mt = 0; mt < 4; mt++)
#pragma unroll
        for (int nt = 0; nt < 4; nt++)
#pragma unroll
            for (int r = 0; r < 4; r++) acc[mt][nt][r] = 0.f;

    int nkt = K / 64;
#pragma unroll
    for (int p = 0; p < 2; p++) {
        uint32_t ab = sb + p * STGH * 2;
        uint32_t bb = ab + 128 * ASTRH * 2;
#pragma unroll
        for (int i = 0; i < 4; i++) {
            int r = lr + 32 * i;
            cpa16(ab + (r * ASTRH + lc) * 2, &A[(size_t)(m0 + r) * K + p * 64 + lc]);
            cpa16(bb + (r * ASTRH + lc) * 2, &Bt[(size_t)(n0 + r) * K + p * 64 + lc]);
        }
        CP_COMMIT();
    }

    for (int kt = 0; kt < nkt; kt++) {
        CP_WAIT(1);
        __syncthreads();

        uint32_t abase = sb + (kt % 3) * STGH * 2;
        uint32_t bbase = abase + 128 * ASTRH * 2;
#pragma unroll
        for (int ks = 0; ks < 4; ks++) {
            unsigned a[4][4], bp[2][4];
#pragma unroll
            for (int mt = 0; mt < 4; mt++)
                ldm4(a[mt],
                     abase + ((wm + mt * 16 + arow) * ASTRH + acol + ks * 16) * 2);
#pragma unroll
            for (int np = 0; np < 2; np++)
                ldm4(bp[np],
                     bbase + ((wn + np * 16 + brow) * ASTRH + bcol + ks * 16) * 2);
#pragma unroll
            for (int mt = 0; mt < 4; mt++)
#pragma unroll
                for (int nt = 0; nt < 4; nt++)
                    mma16(acc[mt][nt], a[mt][0], a[mt][1], a[mt][2], a[mt][3],
                          bp[nt >> 1][(nt & 1) * 2], bp[nt >> 1][(nt & 1) * 2 + 1]);
        }

        if (kt + 2 < nkt) {
            int st = (kt + 2) % 3;
            uint32_t ab = sb + st * STGH * 2;
            uint32_t bb = ab + 128 * ASTRH * 2;
            int kof = (kt + 2) * 64;
#pragma unroll
            for (int i = 0; i < 4; i++) {
                int r = lr + 32 * i;
                cpa16(ab + (r * ASTRH + lc) * 2,
                      &A[(size_t)(m0 + r) * K + kof + lc]);
                cpa16(bb + (r * ASTRH + lc) * 2,
                      &Bt[(size_t)(n0 + r) * K + kof + lc]);
            }
        }
        CP_COMMIT();
    }

#pragma unroll
    for (int mt = 0; mt < 4; mt++)
#pragma unroll
        for (int nt = 0; nt < 4; nt++) {
            int row = m0 + wm + mt * 16 + g;
            int col = n0 + wn + nt * 8 + 2 * t;
            *(float2*)&C[(size_t)row * N + col] =
                make_float2(acc[mt][nt][0], acc[mt][nt][1]);
            *(float2*)&C[(size_t)(row + 8) * N + col] =
                make_float2(acc[mt][nt][2], acc[mt][nt][3]);
        }
}

// ---------------- per-head RMSNorm + RoPE -> fp16 (warp per (token,head)) ---
__global__ void normrope(const int* __restrict__ pos,
                         const float* __restrict__ qw,
                         const float* __restrict__ kw) {
    int gw = (blockIdx.x * blockDim.x + threadIdx.x) >> 5;
    int lane = threadIdx.x & 31;
    if (gw >= TT * (NH + NKV)) return;
    int t = gw / (NH + NKV);
    int hh = gw - t * (NH + NKV);

    const float* src;
    __half* dst;
    const float* w;
    float osc;
    const float QSC = 0.08838834764831845f * 1.4426950408889634f; // scale*log2e
    if (hh < NH) {
        src = g_qkv + (size_t)t * QKVN + hh * HD;
        dst = g_q + (size_t)t * QS + hh * HD;
        w = qw;
        osc = QSC;
    } else {
        int kk = hh - NH;
        src = g_qkv + (size_t)t * QKVN + QS + kk * HD;
        dst = g_k + (size_t)t * KVS + kk * HD;
        w = kw;
        osc = 1.0f;
    }
    float v0 = src[lane], v1 = src[lane + 32], v2 = src[lane + 64], v3 = src[lane + 96];
    float ss = v0 * v0 + v1 * v1 + v2 * v2 + v3 * v3;
#pragma unroll
    for (int o = 16; o; o >>= 1) ss += __shfl_xor_sync(0xffffffffu, ss, o);
    float inv = rsqrtf(ss * (1.0f / 128.0f) + 1e-6f);
    v0 *= inv * w[lane];
    v1 *= inv * w[lane + 32];
    v2 *= inv * w[lane + 64];
    v3 *= inv * w[lane + 96];

    float p = (float)pos[t];
    const float LOG2_THETA = 19.931568569324174f;
    float if0 = exp2f(-LOG2_THETA * (2.0f * lane) * (1.0f / 128.0f));
    float if1 = exp2f(-LOG2_THETA * (2.0f * (lane + 32)) * (1.0f / 128.0f));
    float s0, c0, s1, c1;
    sincosf(p * if0, &s0, &c0);
    sincosf(p * if1, &s1, &c1);
    dst[lane]      = __float2half((v0 * c0 - v2 * s0) * osc);
    dst[lane + 64] = __float2half((v2 * c0 + v0 * s0) * osc);
    dst[lane + 32] = __float2half((v1 * c1 - v3 * s1) * osc);
    dst[lane + 96] = __float2half((v3 * c1 + v1 * s1) * osc);
}

// ---------------- fp16 flash attention: BM=128, BN=128 (R12 + 1 barrier) ----
// 256 threads; warp = 16 q-rows x 128 kv cols. Compute-then-prefetch order:
// the prefetch into buffer nb happens AFTER this iteration's top barrier, and
// nb's readers (iteration kt-1) all passed that barrier => single sync/tile.
#define KSTRH 136
#define VSTRH 136
#define QSTRH 136
#define KSZH (128 * KSTRH)   // 17408 halves
#define VSZH (128 * VSTRH)   // 17408 halves
#define FL_SMEM_BYTES ((2 * KSZH + 2 * VSZH + 128 * QSTRH) * 2)  // 174080

__global__ __launch_bounds__(256, 1)
void flash_h(const __half* __restrict__ gq, const __half* __restrict__ gk,
             const __half* __restrict__ gvT) {
    extern __shared__ __half smf[];
    uint32_t sb = smem_u32(smf);
    uint32_t kbA[2] = {sb, sb + KSZH * 2};
    uint32_t vbA[2] = {sb + 2 * KSZH * 2, sb + (2 * KSZH + VSZH) * 2};
    __half* Qs = smf + 2 * KSZH + 2 * VSZH;
    uint32_t qbase = sb + (2 * KSZH + 2 * VSZH) * 2;

    int tid = threadIdx.x, w = tid >> 5, lane = tid & 31;
    int g = lane >> 2, t = lane & 3;
    int qt = gridDim.x - 1 - blockIdx.x;   // heavy tiles first
    int h = blockIdx.y, kvh = h >> 1;
    int q0 = qt * 128;

    int lane8 = lane & 7, lg = lane >> 3;
    int arow = lane & 15, acol = (lane >> 4) * 8;
    int brow = (lg >> 1) * 8 + lane8, bcol = (lg & 1) * 8;

    // prefetch K/V tile 0 (K: [128 tok][128 d]; V: [128 d][128 tok])
#pragma unroll
    for (int i = 0; i < 8; i++) {
        int idx = tid + 256 * i;
        int r = idx >> 4, c = (idx & 15) * 8;
        cpa16(kbA[0] + (r * KSTRH + c) * 2, &gk[(size_t)r * KVS + kvh * HD + c]);
        cpa16(vbA[0] + (r * VSTRH + c) * 2, &gvT[(size_t)(kvh * HD + r) * TT + c]);
    }
    CP_COMMIT();

    // stage Q tile (fp16, pre-scaled), then fragments -> registers (ldmatrix)
    for (int idx = tid; idx < 128 * 16; idx += 256) {
        int r = idx >> 4, cq = (idx & 15) * 8;
        *(uint4*)&Qs[r * QSTRH + cq] =
            *(const uint4*)&gq[(size_t)(q0 + r) * QS + h * HD + cq];
    }
    __syncthreads();
    unsigned qa[8][4];
#pragma unroll
    for (int ks = 0; ks < 8; ks++)
        ldm4(qa[ks], qbase + ((w * 16 + arow) * QSTRH + ks * 16 + acol) * 2);

    float m_[2] = {-INFINITY, -INFINITY};
    float l_[2] = {0.f, 0.f};
    float O[16][4];
#pragma unroll
    for (int dt = 0; dt < 16; dt++)
#pragma unroll
        for (int r = 0; r < 4; r++) O[dt][r] = 0.f;

    for (int kt = 0; kt <= qt; kt++) {
        int cur = kt & 1;
        CP_WAIT(0);             // only tile kt's group is in flight here
        __syncthreads();

        // prefetch kt+1 into the buffer freed by iteration kt-1
        if (kt < qt) {
            int nb = cur ^ 1, k0n = (kt + 1) * 128;
#pragma unroll
            for (int i = 0; i < 8; i++) {
                int idx = tid + 256 * i;
                int r = idx >> 4, c = (idx & 15) * 8;
                cpa16(kbA[nb] + (r * KSTRH + c) * 2,
                      &gk[(size_t)(k0n + r) * KVS + kvh * HD + c]);
                cpa16(vbA[nb] + (r * VSTRH + c) * 2,
                      &gvT[(size_t)(kvh * HD + r) * TT + k0n + c]);
            }
            CP_COMMIT();
        }

        uint32_t kcur = kbA[cur], vcur = vbA[cur];
        int k0 = kt * 128;

        // S = Q K^T
        float s[16][4];
#pragma unroll
        for (int nt = 0; nt < 16; nt++)
#pragma unroll
            for (int r = 0; r < 4; r++) s[nt][r] = 0.f;
#pragma unroll
        for (int ks = 0; ks < 8; ks++) {
#pragma unroll
            for (int p = 0; p < 8; p++) {
                unsigned kb[4];
                ldm4(kb, kcur + ((p * 16 + brow) * KSTRH + bcol + ks * 16) * 2);
                mma16(s[2 * p], qa[ks][0], qa[ks][1], qa[ks][2], qa[ks][3],
                      kb[0], kb[1]);
                mma16(s[2 * p + 1], qa[ks][0], qa[ks][1], qa[ks][2], qa[ks][3],
                      kb[2], kb[3]);
            }
        }

        // causal mask (diagonal tile only: k0 == q0)
        if (kt == qt) {
            int row0 = q0 + w * 16 + g, row1 = row0 + 8;
#pragma unroll
            for (int nt = 0; nt < 16; nt++) {
                int c0 = k0 + nt * 8 + 2 * t, c1 = c0 + 1;
                if (c0 > row0) s[nt][0] = -1e30f;
                if (c1 > row0) s[nt][1] = -1e30f;
                if (c0 > row1) s[nt][2] = -1e30f;
                if (c1 > row1) s[nt][3] = -1e30f;
            }
        }

        // online softmax, base-2 domain (log2e folded into Q scale)
        float mx0 = -INFINITY, mx1 = -INFINITY;
#pragma unroll
        for (int nt = 0; nt < 16; nt++) {
            mx0 = fmaxf(mx0, fmaxf(s[nt][0], s[nt][1]));
            mx1 = fmaxf(mx1, fmaxf(s[nt][2], s[nt][3]));
        }
        mx0 = fmaxf(mx0, __shfl_xor_sync(0xffffffffu, mx0, 1));
        mx0 = fmaxf(mx0, __shfl_xor_sync(0xffffffffu, mx0, 2));
        mx1 = fmaxf(mx1, __shfl_xor_sync(0xffffffffu, mx1, 1));
        mx1 = fmaxf(mx1, __shfl_xor_sync(0xffffffffu, mx1, 2));
        float mn0 = fmaxf(m_[0], mx0), mn1 = fmaxf(m_[1], mx1);
        float al0 = ex2(m_[0] - mn0), al1 = ex2(m_[1] - mn1);
        m_[0] = mn0; m_[1] = mn1;
        float sum0 = 0.f, sum1 = 0.f;
#pragma unroll
        for (int nt = 0; nt < 16; nt++) {
            s[nt][0] = ex2(s[nt][0] - mn0);
            s[nt][1] = ex2(s[nt][1] - mn0);
            s[nt][2] = ex2(s[nt][2] - mn1);
            s[nt][3] = ex2(s[nt][3] - mn1);
            sum0 += s[nt][0] + s[nt][1];
            sum1 += s[nt][2] + s[nt][3];
        }
        sum0 += __shfl_xor_sync(0xffffffffu, sum0, 1);
        sum0 += __shfl_xor_sync(0xffffffffu, sum0, 2);
        sum1 += __shfl_xor_sync(0xffffffffu, sum1, 1);
        sum1 += __shfl_xor_sync(0xffffffffu, sum1, 2);
        l_[0] = al0 * l_[0] + sum0;
        l_[1] = al1 * l_[1] + sum1;
#pragma unroll
        for (int dt = 0; dt < 16; dt++) {
            O[dt][0] *= al0; O[dt][1] *= al0;
            O[dt][2] *= al1; O[dt][3] *= al1;
        }

        // O += P V  — P packed straight from registers; V frags via ldmatrix
#pragma unroll
        for (int ks2 = 0; ks2 < 8; ks2++) {
            unsigned a0 = pkh2(s[2 * ks2][0], s[2 * ks2][1]);
            unsigned a1 = pkh2(s[2 * ks2][2], s[2 * ks2][3]);
            unsigned a2 = pkh2(s[2 * ks2 + 1][0], s[2 * ks2 + 1][1]);
            unsigned a3 = pkh2(s[2 * ks2 + 1][2], s[2 * ks2 + 1][3]);
#pragma unroll
            for (int p = 0; p < 8; p++) {
                unsigned vb[4];
                ldm4(vb, vcur + ((p * 16 + brow) * VSTRH + bcol + ks2 * 16) * 2);
                mma16(O[2 * p], a0, a1, a2, a3, vb[0], vb[1]);
                mma16(O[2 * p + 1], a0, a1, a2, a3, vb[2], vb[3]);
            }
        }
    }

    // epilogue -> fp16 g_att
    float i0 = 1.f / l_[0], i1 = 1.f / l_[1];
    int row0 = q0 + w * 16 + g;
    __half2* at2 = (__half2*)g_att;
#pragma unroll
    for (int dt = 0; dt < 16; dt++) {
        int col2 = (h * HD + dt * 8 + 2 * t) >> 1;
        at2[(size_t)row0 * (QS / 2) + col2] =
            __floats2half2_rn(O[dt][0] * i0, O[dt][1] * i0);
        at2[(size_t)(row0 + 8) * (QS / 2) + col2] =
            __floats2half2_rn(O[dt][2] * i1, O[dt][3] * i1);
    }
}

// ---------------------------------------------------------------------------
extern "C" void kernel_launch(void* const* d_in, const int* in_sizes, int n_in,
                              void* d_out, int out_size) {
    const int* positions = (const int*)d_in[0];
    const float* hs = (const float*)d_in[1];
    const float* w_qkv = (const float*)d_in[2];
    const float* w_o = (const float*)d_in[3];
    const float* qw = (const float*)d_in[4];
    const float* kw = (const float*)d_in[5];
    float* out = (float*)d_out;

    float* p_qkv;
    __half *p_hst, *p_wqT, *p_woT, *p_q, *p_k, *p_vT, *p_att;
    cudaGetSymbolAddress((void**)&p_qkv, g_qkv);
    cudaGetSymbolAddress((void**)&p_hst, g_hst);
    cudaGetSymbolAddress((void**)&p_wqT, g_wqT);
    cudaGetSymbolAddress((void**)&p_woT, g_woT);
    cudaGetSymbolAddress((void**)&p_q, g_q);
    cudaGetSymbolAddress((void**)&p_k, g_k);
    cudaGetSymbolAddress((void**)&p_vT, g_vT);
    cudaGetSymbolAddress((void**)&p_att, g_att);
    cudaFuncSetAttribute(gemm_h,
                         cudaFuncAttributeMaxDynamicSharedMemorySize, GM_SMEM_BYTES);
    cudaFuncSetAttribute(flash_h,
                         cudaFuncAttributeMaxDynamicSharedMemorySize, FL_SMEM_BYTES);

    // 0) fp16 conversion / weight transposes
    cvt_h<<<(TT * HH / 2 + 255) / 256, 256>>>(hs, (__half2*)p_hst, TT * HH / 2);
    cvt_t<<<dim3(QKVN / 32, HH / 32), dim3(32, 8)>>>(w_qkv, p_wqT, HH, QKVN);
    cvt_t<<<dim3(HH / 32, QS / 32), dim3(32, 8)>>>(w_o, p_woT, QS, HH);
    // 1) QKV projection (fp16 mma, fp32 out)
    gemm_h<<<dim3(QKVN / 128, TT / 128), 256, GM_SMEM_BYTES>>>(
        p_hst, p_wqT, p_qkv, TT, QKVN, HH);
    // 2) per-head RMSNorm + RoPE -> fp16 Q/K ; V transpose -> fp16
    normrope<<<(TT * (NH + NKV)) / 8, 256>>>(positions, qw, kw);
    cvt_tv<<<dim3(KVS / 32, TT / 32), dim3(32, 8)>>>();
    // 3) causal GQA flash attention (fp16 mma, BM=128/BN=128, 1 barrier/tile)
    flash_h<<<dim3(TT / 128, NH), 256, FL_SMEM_BYTES>>>(p_q, p_k, p_vT);
    // 4) output projection
    gemm_h<<<dim3(HH / 128, TT / 128), 256, GM_SMEM_BYTES>>>(
        p_att, p_woT, out, TT, HH, QS);
}